// round 16
// baseline (speedup 1.0000x reference)
#include <cuda_runtime.h>
#include <cuda_bf16.h>
#include <cuda_fp16.h>
#include <math.h>
#include <cstdint>

#define EPS 1e-5f
#define NPATCH 64
#define HS 44
#define NB (NPATCH*HS)          // 2816
#define PLANE 1936
#define IMGSZ (256*1936)

// padded conv geometry
#define PPX 2208
#define MARGIN_LO 128
#define XROWS (MARGIN_LO + NPATCH*PPX + 256)

typedef unsigned long long ull;
__device__ __forceinline__ void fma2(float2 &d, float2 a, float2 b) {
    asm("fma.rn.f32x2 %0, %1, %2, %0;"
        : "+l"(reinterpret_cast<ull&>(d))
        : "l"(reinterpret_cast<ull&>(a)), "l"(reinterpret_cast<ull&>(b)));
}
__device__ __forceinline__ float2 h2f(uint32_t u) {
    __half2 h = *reinterpret_cast<__half2*>(&u);
    return __half22float2(h);
}

// ---------------- mma / ldmatrix / cp.async helpers ----------------
__device__ __forceinline__ uint32_t smem_to_u32(const void* p) {
    uint32_t a;
    asm("{ .reg .u64 t; cvta.to.shared.u64 t, %1; cvt.u32.u64 %0, t; }" : "=r"(a) : "l"(p));
    return a;
}
__device__ __forceinline__ void ldsm_x4(uint32_t a[4], uint32_t addr) {
    asm volatile("ldmatrix.sync.aligned.m8n8.x4.shared.b16 {%0,%1,%2,%3}, [%4];"
        : "=r"(a[0]),"=r"(a[1]),"=r"(a[2]),"=r"(a[3]) : "r"(addr));
}
__device__ __forceinline__ void ldsm_x2_t(uint32_t b[2], uint32_t addr) {
    asm volatile("ldmatrix.sync.aligned.m8n8.x2.trans.shared.b16 {%0,%1}, [%2];"
        : "=r"(b[0]),"=r"(b[1]) : "r"(addr));
}
__device__ __forceinline__ void mma_f16(float c[4], const uint32_t a[4], const uint32_t b[2]) {
    asm volatile("mma.sync.aligned.m16n8k16.row.col.f32.f16.f16.f32 "
        "{%0,%1,%2,%3}, {%4,%5,%6,%7}, {%8,%9}, {%0,%1,%2,%3};"
        : "+f"(c[0]),"+f"(c[1]),"+f"(c[2]),"+f"(c[3])
        : "r"(a[0]),"r"(a[1]),"r"(a[2]),"r"(a[3]), "r"(b[0]),"r"(b[1]));
}
__device__ __forceinline__ void cp16(uint32_t saddr, const void* g) {
    asm volatile("cp.async.cg.shared.global [%0], [%1], 16;" :: "r"(saddr), "l"(g));
}
#define CP_COMMIT() asm volatile("cp.async.commit_group;" ::: "memory")
#define CP_WAIT(n)  asm volatile("cp.async.wait_group %0;" :: "n"(n) : "memory")

// ---------------- static device scratch ----------------
__device__ float g_p [NPATCH*IMGSZ];
__device__ float g_t1[NPATCH*IMGSZ];
__device__ __half g_qkv[(size_t)NPATCH*512*PLANE];
__device__ float g_qkvb[2][512];
__device__ float g_simA[2][12];
__device__ float g_simBsum[2][4];
__device__ float g_outA_sv[2][256];
__device__ float g_outA_sve[2][256];
__device__ float g_outB[2][256];
__device__ __half g_relTh[2][87*72];
__device__ uint32_t g_rvP[2][5632];
// tensor-core operand buffers
__device__ __align__(1024) __half g_xb[(size_t)NPATCH*256*PLANE + 256];
__device__ __align__(1024) __half g_qwh[2][512*256];
__device__ __align__(1024) __half g_qwl[2][512*256];
__device__ __align__(1024) __half g_xc[(size_t)XROWS*256];
__device__ __align__(1024) __half g_wc[9*256*256];

// ---------------- prep ----------------
__global__ void prep_kernel(const float* __restrict__ h_qkv_w, const float* __restrict__ h_bn_qkv,
                            const float* __restrict__ h_bn_sim, const float* __restrict__ h_bn_out,
                            const float* __restrict__ w_qkv_w, const float* __restrict__ w_bn_qkv,
                            const float* __restrict__ w_bn_sim, const float* __restrict__ w_bn_out,
                            const float* __restrict__ conv_w,
                            const float* __restrict__ h_rel, const float* __restrict__ w_rel)
{
    int idx = blockIdx.x * blockDim.x + threadIdx.x;
    const __half zero = __float2half(0.f);

    if (idx < 256*256*9) {
        int co  = idx / 2304;
        int rem = idx - co*2304;
        int ci  = rem / 9;
        int tap = rem - ci*9;
        g_wc[(tap*256 + ci)*256 + co] = __float2half(conv_w[idx]);
    }
    if (idx < MARGIN_LO*256) g_xc[idx] = zero;
    if (idx < 256*256) g_xc[(size_t)(MARGIN_LO + NPATCH*PPX)*256 + idx] = zero;
    for (int z = idx; z < NPATCH*69632; z += 2304*256) {
        int n = z / 69632, e = z - n*69632;
        int py, x, ch;
        if (e < 12288)      { py = 0;  x = e >> 8;              ch = e & 255; }
        else if (e < 24576) { int e2 = e - 12288; py = 45; x = e2 >> 8; ch = e2 & 255; }
        else {
            int e2 = e - 24576;
            py = 1 + (e2 >> 10);
            int r2 = e2 & 1023;
            int xi = r2 >> 8;
            x = (xi == 0) ? 0 : (44 + xi);
            ch = r2 & 255;
        }
        g_xc[((size_t)MARGIN_LO + (size_t)n*PPX + py*48 + x)*256 + ch] = zero;
    }
    if (idx < 2*131072) {
        int ax = idx >> 17;
        int r  = idx & 131071;
        int o  = r & 511;
        int c  = r >> 9;
        const float* bn = ax ? w_bn_qkv : h_bn_qkv;
        const float* W  = ax ? w_qkv_w : h_qkv_w;
        float s = bn[o] * rsqrtf(bn[1536+o] + EPS);
        float wv = W[o*256 + c] * s;
        __half hi = __float2half(wv);
        float lo = wv - __half2float(hi);
        g_qwh[ax][o*256 + c] = hi;
        g_qwl[ax][o*256 + c] = __float2half(lo);
        if (c == 0) g_qkvb[ax][o] = bn[512+o] - bn[1024+o]*s;
    }
    if (idx < 8) {
        int ax = idx >> 2, g = idx & 3;
        const float* bs = ax ? w_bn_sim : h_bn_sim;
        float shsum = 0.f;
        #pragma unroll
        for (int p = 0; p < 3; p++) {
            int ch = p*4 + g;
            float s = bs[ch] * rsqrtf(bs[36+ch] + EPS);
            g_simA[ax][p*4+g] = (p == 0 ? 1.f : 0.1f) * s;
            shsum += bs[12+ch] - bs[24+ch]*s;
        }
        g_simBsum[ax][g] = shsum;
    }
    if (idx < 512) {
        int ax = idx >> 8, cc = idx & 255;
        const float* bo = ax ? w_bn_out : h_bn_out;
        int o1 = 2*cc, o2 = 2*cc + 1;
        float s1 = bo[o1] * rsqrtf(bo[1536+o1] + EPS);
        float s2 = bo[o2] * rsqrtf(bo[1536+o2] + EPS);
        g_outA_sv[ax][cc]  = s1;
        g_outA_sve[ax][cc] = 0.1f * s2;
        g_outB[ax][cc] = (bo[512+o1] - bo[1024+o1]*s1) + (bo[512+o2] - bo[1024+o2]*s2);
    }
    if (idx < 2*87*72) {
        int ax = idx / 6264, r = idx - ax*6264;
        int d = r / 72, c = r - d*72;
        const float* rl = ax ? w_rel : h_rel;
        g_relTh[ax][r] = __float2half(c < 64 ? rl[c*87 + d] : 0.f);
    }
    if (idx < 2*5632) {
        int ax = idx / 5632, r = idx - ax*5632;
        int par = r / 2816, r2 = r - par*2816;
        int dhalf = r2 >> 6, c = r2 & 63;
        const float* rl = ax ? w_rel : h_rel;
        int d0 = 2*dhalf + par;
        float lo = (d0     <= 86) ? rl[(64+c)*87 + 86 - d0]     : 0.f;
        float hi = (d0 + 1 <= 86) ? rl[(64+c)*87 + 86 - d0 - 1] : 0.f;
        __half2 h2v = __halves2half2(__float2half(lo), __float2half(hi));
        g_rvP[ax][par*2816 + dhalf*64 + c] = *reinterpret_cast<uint32_t*>(&h2v);
    }
}

// ---------------- patchify ----------------
__global__ void __launch_bounds__(256,1) patchify_kernel(const float* __restrict__ x)
{
    __shared__ float tile[44*45];
    const int b = blockIdx.x;
    const int np = b >> 8, c = b & 255;
    const int bb_ = np >> 2, i2 = (np >> 1) & 1, j2 = np & 1;
    const float* src = x + ((size_t)(bb_*256 + c)*88 + i2*44)*88 + j2*44;
    float* dp = g_p + (size_t)b*1936;
    const int t = threadIdx.x;
    for (int idx = t; idx < 1936; idx += 256) {
        int y = idx / 44, xq = idx - y*44;
        float v = src[y*88 + xq];
        dp[idx] = v;
        tile[xq*45 + y] = v;
    }
    __syncthreads();
    const size_t base = (size_t)b*1936;
    for (int idx = t; idx < 1936; idx += 256) {
        int r = idx / 44, col = idx - r*44;
        g_xb[base + idx] = __float2half(tile[r*45 + col]);
    }
}

// ---------------- transpose g_t1 [c][x][y] -> fp16 [c][y][x] ----------------
__global__ void __launch_bounds__(256,1) transpose_kernel()
{
    __shared__ float tile[44*45];
    const int b = blockIdx.x;
    const float* src = g_t1 + (size_t)b*1936;
    const int t = threadIdx.x;
    for (int idx = t; idx < 1936; idx += 256) {
        int r = idx / 44, col = idx - r*44;
        tile[col*45 + r] = src[idx];
    }
    __syncthreads();
    const size_t base = (size_t)b*1936;
    for (int idx = t; idx < 1936; idx += 256) {
        int r = idx / 44, col = idx - r*44;
        g_xb[base + idx] = __float2half(tile[r*45 + col]);
    }
}

// ---------------- qkv GEMM v5: fp16 2-pass, fp16 output ----------------
#define QB_A    69632
#define QB_AST  12288
#define QB_ALO  6144
#define GEMM_SMEM (69632 + 2*12288)

__global__ void __launch_bounds__(512,1) qkv_gemm_kernel(int ax)
{
    extern __shared__ char smc[];
    const uint32_t sbase = smem_to_u32(smc);
    const int t = threadIdx.x;
    const int wid = t >> 5, lane = t & 31;
    const int ntile = blockIdx.x;
    const int n     = blockIdx.y;
    const int pxw = ntile * 128;
    const int wm = wid & 1, wn = wid >> 1;
    const __half* qwh = g_qwh[ax];
    const __half* qwl = g_qwl[ax];

    for (int j = t; j < 4096; j += 512) {
        int row = j >> 4, unit = j & 15;
        const __half* g = g_xb + ((size_t)(n*256 + row))*1936 + pxw + unit*8;
        cp16(sbase + row*272 + unit*16, g);
    }
    CP_COMMIT();
    CP_WAIT(0);
    __syncthreads();

    auto load_A = [&](int mtile, int kc, int stage) {
        const int mrow0 = mtile*128;
        const uint32_t sA = sbase + QB_A + stage*QB_AST;
        int o = t;
        int hl   = o & 1;
        int half = (o >> 1) & 1;
        int row  = o >> 2;
        const __half* g = (hl ? qwl : qwh) + (size_t)(mrow0 + row)*256 + kc*16 + half*8;
        cp16(sA + hl*QB_ALO + row*48 + half*16, g);
    };

    for (int mtile = 0; mtile < 4; mtile++) {
        float acc[4][2][4];
        #pragma unroll
        for (int mf = 0; mf < 4; mf++)
            #pragma unroll
            for (int nf = 0; nf < 2; nf++)
                #pragma unroll
                for (int k = 0; k < 4; k++) acc[mf][nf][k] = 0.f;

        load_A(mtile, 0, 0); CP_COMMIT();
        load_A(mtile, 1, 1); CP_COMMIT();

        for (int kc = 0; kc < 16; kc++) {
            const int stage = kc & 1;
            if (kc + 1 < 16) { CP_WAIT(1); }
            else             { CP_WAIT(0); }
            __syncthreads();

            const uint32_t sA = sbase + QB_A + stage*QB_AST;
            uint32_t Ah[4][4], Al[4][4], B[2][2];
            #pragma unroll
            for (int mf = 0; mf < 4; mf++) {
                uint32_t a_off = (wm*64 + mf*16 + (lane & 15))*48 + (lane >> 4)*16;
                ldsm_x4(Ah[mf], sA + a_off);
                ldsm_x4(Al[mf], sA + QB_ALO + a_off);
            }
            #pragma unroll
            for (int nf = 0; nf < 2; nf++) {
                uint32_t b_off = (kc*16 + (lane & 15))*272 + (wn*16 + nf*8)*2;
                ldsm_x2_t(B[nf], sbase + b_off);
            }
            __syncthreads();
            if (kc + 2 < 16) { load_A(mtile, kc+2, stage); CP_COMMIT(); }
            #pragma unroll
            for (int mf = 0; mf < 4; mf++)
                #pragma unroll
                for (int nf = 0; nf < 2; nf++) {
                    mma_f16(acc[mf][nf], Ah[mf], B[nf]);
                    mma_f16(acc[mf][nf], Al[mf], B[nf]);
                }
        }

        const int mrow0 = mtile*128;
        #pragma unroll
        for (int mf = 0; mf < 4; mf++) {
            int row0 = mrow0 + wm*64 + mf*16 + (lane >> 2);
            #pragma unroll
            for (int nf = 0; nf < 2; nf++) {
                int pos = pxw + wn*16 + nf*8 + (lane & 3)*2;
                if (pos < 1936) {
                    float b0 = g_qkvb[ax][row0];
                    float b1 = g_qkvb[ax][row0 + 8];
                    *(__half2*)(g_qkv + ((size_t)n*512 + row0)*1936 + pos) =
                        __floats2half2_rn(acc[mf][nf][0] + b0, acc[mf][nf][1] + b0);
                    *(__half2*)(g_qkv + ((size_t)n*512 + row0 + 8)*1936 + pos) =
                        __floats2half2_rn(acc[mf][nf][2] + b1, acc[mf][nf][3] + b1);
                }
            }
        }
        __syncthreads();
    }
}

// ---------------- fused axial attention v10: fp16 q/k/v in smem ----------------
// byte offsets: qkTh[44][264]h@0 | vSh[256][56]h@23232 | simS f32@51904 |
//               rTh@82880 | rvS@105408 | resS@127936 ; staging reuses [0,51904)
#define XB_QKT 0
#define XB_V   23232
#define XB_SIM 51904
#define XB_RTH 82880
#define XB_RVP 105408
#define XB_RES 127936
#define AX_SMEM 172992

template<int AX>
__global__ void __launch_bounds__(1024,1) axial_kernel()
{
    extern __shared__ char smb[];
    __half* qkTh = (__half*)(smb + XB_QKT);
    __half* vSh  = (__half*)(smb + XB_V);
    float*  simS = (float*)(smb + XB_SIM);
    const __half* rTh = (const __half*)(smb + XB_RTH);
    uint32_t* rvS = (uint32_t*)(smb + XB_RVP);
    float* resS = (float*)(smb + XB_RES);
    float* stg  = (float*)smb;          // epilogue staging (aliases qkTh/vSh)

    const int t  = threadIdx.x;
    const int bb = blockIdx.x;
    const int n  = bb / 44;
    const int s  = bb - n*44;

    // load qkv slice (raw fp16) + rel tables (+ residual for AX=1)
    {
        const __half* qsrc = g_qkv + (size_t)n*512*1936 + s*44;
        for (int idx = t; idx < 5632; idx += 1024) {
            int o = idx / 11, q = idx - o*11;
            uint2 u2 = *(const uint2*)(qsrc + (size_t)o*1936 + q*4);
            int g = o >> 7, wi = o & 127;
            if (wi < 64) {
                int col = g*64 + wi;
                const __half* hp = (const __half*)&u2;
                qkTh[(q*4+0)*264 + col] = hp[0];
                qkTh[(q*4+1)*264 + col] = hp[1];
                qkTh[(q*4+2)*264 + col] = hp[2];
                qkTh[(q*4+3)*264 + col] = hp[3];
            } else {
                *(uint2*)(vSh + (g*64 + wi - 64)*56 + q*4) = u2;
            }
        }
        const uint32_t* rthG = (const uint32_t*)g_relTh[AX];
        uint32_t* rthS = (uint32_t*)(smb + XB_RTH);
        for (int idx = t; idx < 3132; idx += 1024) rthS[idx] = rthG[idx];
        for (int idx = t; idx < 5632; idx += 1024) rvS[idx] = g_rvP[AX][idx];
        if (AX == 1) {
            const float4* rsrc = (const float4*)(g_p + (size_t)n*IMGSZ + s*44);
            float4* rd = (float4*)resS;
            for (int idx = t; idx < 2816; idx += 1024) {
                int ch = idx / 11, q = idx - ch*11;
                rd[idx] = rsrc[ch*484 + q];
            }
        }
    }
    __syncthreads();

    // sim: thread handles (i,j) for a group PAIR; q/k fp16
    for (int e2 = t; e2 < 3872; e2 += 1024) {
        int gp = e2 / 1936;
        int r = e2 - gp*1936;
        int i = r / 44;
        int j = r - i*44;
        const uint4* rq = (const uint4*)(rTh + (i - j + 43)*72);
        const uint4* rk = (const uint4*)(rTh + (j - i + 43)*72 + 32);
        float2 qk2[2], qr2[2], kr2[2];
        #pragma unroll
        for (int gg = 0; gg < 2; gg++) {
            qk2[gg] = make_float2(0.f, 0.f);
            qr2[gg] = make_float2(0.f, 0.f);
            kr2[gg] = make_float2(0.f, 0.f);
        }
        #pragma unroll
        for (int cc = 0; cc < 4; cc++) {
            uint4 rqu = rq[cc], rku = rk[cc];
            float2 rq0 = h2f(rqu.x), rq1 = h2f(rqu.y), rq2 = h2f(rqu.z), rq3 = h2f(rqu.w);
            float2 rk0 = h2f(rku.x), rk1 = h2f(rku.y), rk2 = h2f(rku.z), rk3 = h2f(rku.w);
            #pragma unroll
            for (int gg = 0; gg < 2; gg++) {
                int g = gp*2 + gg;
                uint4 qu = ((const uint4*)(qkTh + i*264 + g*64))[cc];
                uint4 ku = ((const uint4*)(qkTh + j*264 + g*64 + 32))[cc];
                float2 qa = h2f(qu.x), qb = h2f(qu.y), qc = h2f(qu.z), qd = h2f(qu.w);
                float2 ka = h2f(ku.x), kb = h2f(ku.y), kc2 = h2f(ku.z), kd = h2f(ku.w);
                fma2(qk2[gg], qa, ka); fma2(qk2[gg], qb, kb);
                fma2(qk2[gg], qc, kc2); fma2(qk2[gg], qd, kd);
                fma2(qr2[gg], qa, rq0); fma2(qr2[gg], qb, rq1);
                fma2(qr2[gg], qc, rq2); fma2(qr2[gg], qd, rq3);
                fma2(kr2[gg], ka, rk0); fma2(kr2[gg], kb, rk1);
                fma2(kr2[gg], kc2, rk2); fma2(kr2[gg], kd, rk3);
            }
        }
        #pragma unroll
        for (int gg = 0; gg < 2; gg++) {
            int g = gp*2 + gg;
            float qk = qk2[gg].x + qk2[gg].y;
            float qr = qr2[gg].x + qr2[gg].y;
            float kr = kr2[gg].x + kr2[gg].y;
            simS[g*1936 + r] = g_simA[AX][g]*qk + g_simA[AX][4+g]*qr + g_simA[AX][8+g]*kr + g_simBsum[AX][g];
        }
    }
    __syncthreads();

    // softmax: warp per row
    {
        const int wid = t >> 5, lane = t & 31;
        #pragma unroll
        for (int k = 0; k < 6; k++) {
            int r = wid + 32*k;
            if (r < 176) {
                float* row = simS + (r/44)*1936 + (r - (r/44)*44)*44;
                float v1 = row[lane];
                float v2 = (lane < 12) ? row[lane+32] : -1e30f;
                float m = fmaxf(v1, v2);
                #pragma unroll
                for (int off = 16; off; off >>= 1) m = fmaxf(m, __shfl_xor_sync(0xffffffffu, m, off));
                float e1 = __expf(v1 - m);
                float e2 = (lane < 12) ? __expf(v2 - m) : 0.f;
                float su = e1 + e2;
                #pragma unroll
                for (int off = 16; off; off >>= 1) su += __shfl_xor_sync(0xffffffffu, su, off);
                float inv = 1.f / su;
                row[lane] = e1 * inv;
                if (lane < 12) row[lane+32] = e2 * inv;
            }
        }
    }
    __syncthreads();

    // output: load v (fp16) into regs, THEN barrier (staging aliases vSh/qkTh)
    {
        const int ch = t & 255, qtr = t >> 8;
        const int g = ch >> 6, c = ch & 63;
        float2 v2[22];
        {
            const uint4* vp = (const uint4*)(vSh + ch*56);
            #pragma unroll
            for (int q = 0; q < 5; q++) {
                uint4 u = vp[q];
                v2[4*q+0] = h2f(u.x); v2[4*q+1] = h2f(u.y);
                v2[4*q+2] = h2f(u.z); v2[4*q+3] = h2f(u.w);
            }
            uint2 tail = *(const uint2*)(vSh + ch*56 + 40);
            v2[20] = h2f(tail.x); v2[21] = h2f(tail.y);
        }
        __syncthreads();   // all v reads done before staging overwrites the region

        const float aSV  = g_outA_sv[AX][ch];
        const float aSVE = g_outA_sve[AX][ch];
        const float bO   = g_outB[AX][ch];
        #pragma unroll 1
        for (int ii = 0; ii < 11; ii++) {
            int i = qtr*11 + ii;
            const float2* sr2 = (const float2*)(simS + g*1936 + i*44);
            int b0 = 43 - i;
            const uint32_t* wrow = rvS + (b0 & 1)*2816 + (b0 >> 1)*64 + c;
            float2 sv2 = make_float2(0.f, 0.f), sve2 = make_float2(0.f, 0.f);
            #pragma unroll
            for (int p = 0; p < 22; p++) {
                float2 s2 = sr2[p];
                fma2(sv2, s2, v2[p]);
                fma2(sve2, s2, h2f(wrow[p*64]));
            }
            float val = fmaf(aSV, sv2.x + sv2.y, fmaf(aSVE, sve2.x + sve2.y, bO));
            if (AX == 0) {
                stg[ch*44 + i] = val;
            } else {
                stg[i*256 + ch] = val + resS[ch*44 + i];
            }
        }
    }
    __syncthreads();
    if (AX == 0) {
        float* out = g_t1;
        const float4* st4 = (const float4*)stg;
        for (int idx = t; idx < 2816; idx += 1024) {
            int ch = idx / 11, q = idx - ch*11;
            *(float4*)(out + ((size_t)(n*256 + ch))*1936 + s*44 + q*4) = st4[idx];
        }
    } else {
        const size_t rowbase = ((size_t)MARGIN_LO + (size_t)n*PPX + (size_t)(s+1)*48 + 1)*256;
        for (int idx = t; idx < 11264; idx += 1024) {
            int i = idx >> 8, ch = idx & 255;
            g_xc[rowbase + (size_t)i*256 + ch] = __float2half(stg[i*256 + ch]);
        }
    }
}

// ---------------- tensor-core conv3x3 v3: fp16 single-pass ----------------
#define C3STAGE 14592
#define C3_B    6144
#define CONV_SMEM (3*C3STAGE + 1024)

__global__ void __launch_bounds__(512,1) conv_mma_kernel(const float* __restrict__ conv_b,
                                                         float* __restrict__ out)
{
    extern __shared__ char smc[];
    const uint32_t sbase = smem_to_u32(smc);
    const int t = threadIdx.x;
    const int wid = t >> 5, lane = t & 31;
    const int bb = blockIdx.x;
    const int n = bb / 18;
    const int widx = bb - n*18;
    const int pxw = widx * 128;
    const int wm = wid & 1, wn = wid >> 1;

    float* biasS = (float*)(smc + 3*C3STAGE);
    if (t < 256) biasS[t] = conv_b[t];

    const long long arow0 = (long long)MARGIN_LO + (long long)n*PPX + pxw;

    auto load_chunk = [&](int kc, int stage) {
        const int tap = kc >> 4, sub = kc & 15;
        const int offr = (tap/3 - 1)*48 + (tap%3 - 1);
        const long long abase = arow0 + offr;
        const uint32_t sA = sbase + stage*C3STAGE;
        const uint32_t sB = sA + C3_B;
        #pragma unroll
        for (int i = 0; i < 2; i++) {
            int o = t + 512*i;
            if (o < 256) {
                int half = o & 1;
                int row  = o >> 1;
                const __half* g = g_xc + ((size_t)(abase + row))*256 + sub*16 + half*8;
                cp16(sA + row*48 + half*16, g);
            } else if (o < 768) {
                int o2 = o - 256;
                int krow = o2 >> 5, unit = o2 & 31;
                const __half* g = g_wc + ((size_t)(tap*256 + sub*16 + krow))*256 + unit*8;
                cp16(sB + krow*528 + unit*16, g);
            }
        }
    };

    float acc[4][4][4];
    #pragma unroll
    for (int mf = 0; mf < 4; mf++)
        #pragma unroll
        for (int nf = 0; nf < 4; nf++)
            #pragma unroll
            for (int k = 0; k < 4; k++) acc[mf][nf][k] = 0.f;

    load_chunk(0, 0); CP_COMMIT();
    load_chunk(1, 1); CP_COMMIT();

    for (int kc = 0; kc < 144; kc++) {
        const int stage = kc % 3;
        if (kc + 2 < 144) { load_chunk(kc+2, (kc+2)%3); CP_COMMIT(); CP_WAIT(2); }
        else if (kc + 1 < 144) { CP_WAIT(1); }
        else { CP_WAIT(0); }
        __syncthreads();

        const uint32_t sA = sbase + stage*C3STAGE;
        const uint32_t sB = sA + C3_B;

        uint32_t A[4][4], B[4][2];
        #pragma unroll
        for (int mf = 0; mf < 4; mf++) {
            uint32_t a_off = (wm*64 + mf*16 + (lane & 15))*48 + (lane >> 4)*16;
            ldsm_x4(A[mf], sA + a_off);
        }
        #pragma unroll
        for (int nf = 0; nf < 4; nf++) {
            uint32_t b_off = (lane & 15)*528 + (wn*32 + nf*8)*2;
            ldsm_x2_t(B[nf], sB + b_off);
        }
        #pragma unroll
        for (int mf = 0; mf < 4; mf++)
            #pragma unroll
            for (int nf = 0; nf < 4; nf++)
                mma_f16(acc[mf][nf], A[mf], B[nf]);
        __syncthreads();
    }

    const int b_ = n >> 2, i2 = (n >> 1) & 1, j2 = n & 1;
    #pragma unroll
    for (int mf = 0; mf < 4; mf++) {
        #pragma unroll
        for (int half = 0; half < 2; half++) {
            int px = pxw + wm*64 + mf*16 + (lane >> 2) + half*8;
            int py = px / 48, pxx = px - py*48;
            bool valid = (py >= 1 && py <= 44) && (pxx >= 1 && pxx <= 44);
            if (!valid) continue;
            size_t ob = ((size_t)(b_*256))*7744 + (size_t)(i2*44 + (py-1))*88 + j2*44 + (pxx-1);
            #pragma unroll
            for (int nf = 0; nf < 4; nf++) {
                int co = wn*32 + nf*8 + (lane & 3)*2;
                out[ob + (size_t)co*7744]     = acc[mf][nf][half*2+0] + biasS[co];
                out[ob + (size_t)(co+1)*7744] = acc[mf][nf][half*2+1] + biasS[co+1];
            }
        }
    }
}

// ---------------- launch ----------------
extern "C" void kernel_launch(void* const* d_in, const int* in_sizes, int n_in,
                              void* d_out, int out_size)
{
    const float* x        = (const float*)d_in[0];
    const float* h_qkv_w  = (const float*)d_in[1];
    const float* h_bn_qkv = (const float*)d_in[2];
    const float* h_bn_sim = (const float*)d_in[3];
    const float* h_bn_out = (const float*)d_in[4];
    const float* h_rel    = (const float*)d_in[5];
    const float* w_qkv_w  = (const float*)d_in[6];
    const float* w_bn_qkv = (const float*)d_in[7];
    const float* w_bn_sim = (const float*)d_in[8];
    const float* w_bn_out = (const float*)d_in[9];
    const float* w_rel    = (const float*)d_in[10];
    const float* conv_w   = (const float*)d_in[11];
    const float* conv_b   = (const float*)d_in[12];
    float* out = (float*)d_out;

    cudaFuncSetAttribute(axial_kernel<0>,  cudaFuncAttributeMaxDynamicSharedMemorySize, AX_SMEM);
    cudaFuncSetAttribute(axial_kernel<1>,  cudaFuncAttributeMaxDynamicSharedMemorySize, AX_SMEM);
    cudaFuncSetAttribute(qkv_gemm_kernel,  cudaFuncAttributeMaxDynamicSharedMemorySize, GEMM_SMEM);
    cudaFuncSetAttribute(conv_mma_kernel,  cudaFuncAttributeMaxDynamicSharedMemorySize, CONV_SMEM);

    prep_kernel<<<(256*256*9 + 255)/256, 256>>>(h_qkv_w, h_bn_qkv, h_bn_sim, h_bn_out,
                                                w_qkv_w, w_bn_qkv, w_bn_sim, w_bn_out,
                                                conv_w, h_rel, w_rel);
    patchify_kernel<<<NPATCH*256, 256>>>(x);
    qkv_gemm_kernel<<<dim3(16,NPATCH), 512, GEMM_SMEM>>>(0);
    axial_kernel<0><<<NB, 1024, AX_SMEM>>>();
    transpose_kernel<<<NPATCH*256, 256>>>();
    qkv_gemm_kernel<<<dim3(16,NPATCH), 512, GEMM_SMEM>>>(1);
    axial_kernel<1><<<NB, 1024, AX_SMEM>>>();
    conv_mma_kernel<<<NPATCH*18, 512, CONV_SMEM>>>(conv_b, out);
}

// round 17
// speedup vs baseline: 1.0230x; 1.0230x over previous
#include <cuda_runtime.h>
#include <cuda_bf16.h>
#include <cuda_fp16.h>
#include <math.h>
#include <cstdint>

#define EPS 1e-5f
#define NPATCH 64
#define HS 44
#define NB (NPATCH*HS)          // 2816
#define PLANE 1936
#define IMGSZ (256*1936)

// padded conv geometry
#define PPX 2208
#define MARGIN_LO 128
#define XROWS (MARGIN_LO + NPATCH*PPX + 256)

typedef unsigned long long ull;
__device__ __forceinline__ void fma2(float2 &d, float2 a, float2 b) {
    asm("fma.rn.f32x2 %0, %1, %2, %0;"
        : "+l"(reinterpret_cast<ull&>(d))
        : "l"(reinterpret_cast<ull&>(a)), "l"(reinterpret_cast<ull&>(b)));
}
__device__ __forceinline__ float2 h2f(uint32_t u) {
    __half2 h = *reinterpret_cast<__half2*>(&u);
    return __half22float2(h);
}

// ---------------- mma / ldmatrix / cp.async helpers ----------------
__device__ __forceinline__ uint32_t smem_to_u32(const void* p) {
    uint32_t a;
    asm("{ .reg .u64 t; cvta.to.shared.u64 t, %1; cvt.u32.u64 %0, t; }" : "=r"(a) : "l"(p));
    return a;
}
__device__ __forceinline__ void ldsm_x4(uint32_t a[4], uint32_t addr) {
    asm volatile("ldmatrix.sync.aligned.m8n8.x4.shared.b16 {%0,%1,%2,%3}, [%4];"
        : "=r"(a[0]),"=r"(a[1]),"=r"(a[2]),"=r"(a[3]) : "r"(addr));
}
__device__ __forceinline__ void ldsm_x2_t(uint32_t b[2], uint32_t addr) {
    asm volatile("ldmatrix.sync.aligned.m8n8.x2.trans.shared.b16 {%0,%1}, [%2];"
        : "=r"(b[0]),"=r"(b[1]) : "r"(addr));
}
__device__ __forceinline__ void mma_f16(float c[4], const uint32_t a[4], const uint32_t b[2]) {
    asm volatile("mma.sync.aligned.m16n8k16.row.col.f32.f16.f16.f32 "
        "{%0,%1,%2,%3}, {%4,%5,%6,%7}, {%8,%9}, {%0,%1,%2,%3};"
        : "+f"(c[0]),"+f"(c[1]),"+f"(c[2]),"+f"(c[3])
        : "r"(a[0]),"r"(a[1]),"r"(a[2]),"r"(a[3]), "r"(b[0]),"r"(b[1]));
}
__device__ __forceinline__ void cp16(uint32_t saddr, const void* g) {
    asm volatile("cp.async.cg.shared.global [%0], [%1], 16;" :: "r"(saddr), "l"(g));
}
#define CP_COMMIT() asm volatile("cp.async.commit_group;" ::: "memory")
#define CP_WAIT(n)  asm volatile("cp.async.wait_group %0;" :: "n"(n) : "memory")

// ---------------- static device scratch ----------------
__device__ float g_p [NPATCH*IMGSZ];
__device__ __half g_t1[NPATCH*IMGSZ];                // fp16 inter-axial intermediate
__device__ __half g_qkv[(size_t)NPATCH*512*PLANE];
__device__ float g_qkvb[2][512];
__device__ float g_simA[2][12];
__device__ float g_simBsum[2][4];
__device__ float g_outA_sv[2][256];
__device__ float g_outA_sve[2][256];
__device__ float g_outB[2][256];
__device__ __half g_relTh[2][87*72];
__device__ uint32_t g_rvP[2][5632];
// tensor-core operand buffers
__device__ __align__(1024) __half g_xb[(size_t)NPATCH*256*PLANE + 256];
__device__ __align__(1024) __half g_qwh[2][512*256];
__device__ __align__(1024) __half g_qwl[2][512*256];
__device__ __align__(1024) __half g_xc[(size_t)XROWS*256];
__device__ __align__(1024) __half g_wc[9*256*256];

// ---------------- prep ----------------
__global__ void prep_kernel(const float* __restrict__ h_qkv_w, const float* __restrict__ h_bn_qkv,
                            const float* __restrict__ h_bn_sim, const float* __restrict__ h_bn_out,
                            const float* __restrict__ w_qkv_w, const float* __restrict__ w_bn_qkv,
                            const float* __restrict__ w_bn_sim, const float* __restrict__ w_bn_out,
                            const float* __restrict__ conv_w,
                            const float* __restrict__ h_rel, const float* __restrict__ w_rel)
{
    int idx = blockIdx.x * blockDim.x + threadIdx.x;
    const __half zero = __float2half(0.f);

    if (idx < 256*256*9) {
        int co  = idx / 2304;
        int rem = idx - co*2304;
        int ci  = rem / 9;
        int tap = rem - ci*9;
        g_wc[(tap*256 + ci)*256 + co] = __float2half(conv_w[idx]);
    }
    if (idx < MARGIN_LO*256) g_xc[idx] = zero;
    if (idx < 256*256) g_xc[(size_t)(MARGIN_LO + NPATCH*PPX)*256 + idx] = zero;
    for (int z = idx; z < NPATCH*69632; z += 2304*256) {
        int n = z / 69632, e = z - n*69632;
        int py, x, ch;
        if (e < 12288)      { py = 0;  x = e >> 8;              ch = e & 255; }
        else if (e < 24576) { int e2 = e - 12288; py = 45; x = e2 >> 8; ch = e2 & 255; }
        else {
            int e2 = e - 24576;
            py = 1 + (e2 >> 10);
            int r2 = e2 & 1023;
            int xi = r2 >> 8;
            x = (xi == 0) ? 0 : (44 + xi);
            ch = r2 & 255;
        }
        g_xc[((size_t)MARGIN_LO + (size_t)n*PPX + py*48 + x)*256 + ch] = zero;
    }
    if (idx < 2*131072) {
        int ax = idx >> 17;
        int r  = idx & 131071;
        int o  = r & 511;
        int c  = r >> 9;
        const float* bn = ax ? w_bn_qkv : h_bn_qkv;
        const float* W  = ax ? w_qkv_w : h_qkv_w;
        float s = bn[o] * rsqrtf(bn[1536+o] + EPS);
        float wv = W[o*256 + c] * s;
        __half hi = __float2half(wv);
        float lo = wv - __half2float(hi);
        g_qwh[ax][o*256 + c] = hi;
        g_qwl[ax][o*256 + c] = __float2half(lo);
        if (c == 0) g_qkvb[ax][o] = bn[512+o] - bn[1024+o]*s;
    }
    if (idx < 8) {
        int ax = idx >> 2, g = idx & 3;
        const float* bs = ax ? w_bn_sim : h_bn_sim;
        float shsum = 0.f;
        #pragma unroll
        for (int p = 0; p < 3; p++) {
            int ch = p*4 + g;
            float s = bs[ch] * rsqrtf(bs[36+ch] + EPS);
            g_simA[ax][p*4+g] = (p == 0 ? 1.f : 0.1f) * s;
            shsum += bs[12+ch] - bs[24+ch]*s;
        }
        g_simBsum[ax][g] = shsum;
    }
    if (idx < 512) {
        int ax = idx >> 8, cc = idx & 255;
        const float* bo = ax ? w_bn_out : h_bn_out;
        int o1 = 2*cc, o2 = 2*cc + 1;
        float s1 = bo[o1] * rsqrtf(bo[1536+o1] + EPS);
        float s2 = bo[o2] * rsqrtf(bo[1536+o2] + EPS);
        g_outA_sv[ax][cc]  = s1;
        g_outA_sve[ax][cc] = 0.1f * s2;
        g_outB[ax][cc] = (bo[512+o1] - bo[1024+o1]*s1) + (bo[512+o2] - bo[1024+o2]*s2);
    }
    if (idx < 2*87*72) {
        int ax = idx / 6264, r = idx - ax*6264;
        int d = r / 72, c = r - d*72;
        const float* rl = ax ? w_rel : h_rel;
        g_relTh[ax][r] = __float2half(c < 64 ? rl[c*87 + d] : 0.f);
    }
    if (idx < 2*5632) {
        int ax = idx / 5632, r = idx - ax*5632;
        int par = r / 2816, r2 = r - par*2816;
        int dhalf = r2 >> 6, c = r2 & 63;
        const float* rl = ax ? w_rel : h_rel;
        int d0 = 2*dhalf + par;
        float lo = (d0     <= 86) ? rl[(64+c)*87 + 86 - d0]     : 0.f;
        float hi = (d0 + 1 <= 86) ? rl[(64+c)*87 + 86 - d0 - 1] : 0.f;
        __half2 h2v = __halves2half2(__float2half(lo), __float2half(hi));
        g_rvP[ax][par*2816 + dhalf*64 + c] = *reinterpret_cast<uint32_t*>(&h2v);
    }
}

// ---------------- patchify ----------------
__global__ void __launch_bounds__(256,1) patchify_kernel(const float* __restrict__ x)
{
    __shared__ float tile[44*45];
    const int b = blockIdx.x;
    const int np = b >> 8, c = b & 255;
    const int bb_ = np >> 2, i2 = (np >> 1) & 1, j2 = np & 1;
    const float* src = x + ((size_t)(bb_*256 + c)*88 + i2*44)*88 + j2*44;
    float* dp = g_p + (size_t)b*1936;
    const int t = threadIdx.x;
    for (int idx = t; idx < 1936; idx += 256) {
        int y = idx / 44, xq = idx - y*44;
        float v = src[y*88 + xq];
        dp[idx] = v;
        tile[xq*45 + y] = v;
    }
    __syncthreads();
    const size_t base = (size_t)b*1936;
    for (int idx = t; idx < 1936; idx += 256) {
        int r = idx / 44, col = idx - r*44;
        g_xb[base + idx] = __float2half(tile[r*45 + col]);
    }
}

// ---------------- transpose g_t1(fp16) [c][x][y] -> fp16 [c][y][x] ----------------
__global__ void __launch_bounds__(256,1) transpose_kernel()
{
    __shared__ __half tile[44*45];
    const int b = blockIdx.x;
    const __half* src = g_t1 + (size_t)b*1936;
    const int t = threadIdx.x;
    for (int idx = t; idx < 1936; idx += 256) {
        int r = idx / 44, col = idx - r*44;
        tile[col*45 + r] = src[idx];
    }
    __syncthreads();
    const size_t base = (size_t)b*1936;
    for (int idx = t; idx < 1936; idx += 256) {
        int r = idx / 44, col = idx - r*44;
        g_xb[base + idx] = tile[r*45 + col];
    }
}

// ---------------- qkv GEMM v5: fp16 2-pass, fp16 output ----------------
#define QB_A    69632
#define QB_AST  12288
#define QB_ALO  6144
#define GEMM_SMEM (69632 + 2*12288)

__global__ void __launch_bounds__(512,1) qkv_gemm_kernel(int ax)
{
    extern __shared__ char smc[];
    const uint32_t sbase = smem_to_u32(smc);
    const int t = threadIdx.x;
    const int wid = t >> 5, lane = t & 31;
    const int ntile = blockIdx.x;
    const int n     = blockIdx.y;
    const int pxw = ntile * 128;
    const int wm = wid & 1, wn = wid >> 1;
    const __half* qwh = g_qwh[ax];
    const __half* qwl = g_qwl[ax];

    for (int j = t; j < 4096; j += 512) {
        int row = j >> 4, unit = j & 15;
        const __half* g = g_xb + ((size_t)(n*256 + row))*1936 + pxw + unit*8;
        cp16(sbase + row*272 + unit*16, g);
    }
    CP_COMMIT();
    CP_WAIT(0);
    __syncthreads();

    auto load_A = [&](int mtile, int kc, int stage) {
        const int mrow0 = mtile*128;
        const uint32_t sA = sbase + QB_A + stage*QB_AST;
        int o = t;
        int hl   = o & 1;
        int half = (o >> 1) & 1;
        int row  = o >> 2;
        const __half* g = (hl ? qwl : qwh) + (size_t)(mrow0 + row)*256 + kc*16 + half*8;
        cp16(sA + hl*QB_ALO + row*48 + half*16, g);
    };

    for (int mtile = 0; mtile < 4; mtile++) {
        float acc[4][2][4];
        #pragma unroll
        for (int mf = 0; mf < 4; mf++)
            #pragma unroll
            for (int nf = 0; nf < 2; nf++)
                #pragma unroll
                for (int k = 0; k < 4; k++) acc[mf][nf][k] = 0.f;

        load_A(mtile, 0, 0); CP_COMMIT();
        load_A(mtile, 1, 1); CP_COMMIT();

        for (int kc = 0; kc < 16; kc++) {
            const int stage = kc & 1;
            if (kc + 1 < 16) { CP_WAIT(1); }
            else             { CP_WAIT(0); }
            __syncthreads();

            const uint32_t sA = sbase + QB_A + stage*QB_AST;
            uint32_t Ah[4][4], Al[4][4], B[2][2];
            #pragma unroll
            for (int mf = 0; mf < 4; mf++) {
                uint32_t a_off = (wm*64 + mf*16 + (lane & 15))*48 + (lane >> 4)*16;
                ldsm_x4(Ah[mf], sA + a_off);
                ldsm_x4(Al[mf], sA + QB_ALO + a_off);
            }
            #pragma unroll
            for (int nf = 0; nf < 2; nf++) {
                uint32_t b_off = (kc*16 + (lane & 15))*272 + (wn*16 + nf*8)*2;
                ldsm_x2_t(B[nf], sbase + b_off);
            }
            __syncthreads();
            if (kc + 2 < 16) { load_A(mtile, kc+2, stage); CP_COMMIT(); }
            #pragma unroll
            for (int mf = 0; mf < 4; mf++)
                #pragma unroll
                for (int nf = 0; nf < 2; nf++) {
                    mma_f16(acc[mf][nf], Ah[mf], B[nf]);
                    mma_f16(acc[mf][nf], Al[mf], B[nf]);
                }
        }

        const int mrow0 = mtile*128;
        #pragma unroll
        for (int mf = 0; mf < 4; mf++) {
            int row0 = mrow0 + wm*64 + mf*16 + (lane >> 2);
            #pragma unroll
            for (int nf = 0; nf < 2; nf++) {
                int pos = pxw + wn*16 + nf*8 + (lane & 3)*2;
                if (pos < 1936) {
                    float b0 = g_qkvb[ax][row0];
                    float b1 = g_qkvb[ax][row0 + 8];
                    *(__half2*)(g_qkv + ((size_t)n*512 + row0)*1936 + pos) =
                        __floats2half2_rn(acc[mf][nf][0] + b0, acc[mf][nf][1] + b0);
                    *(__half2*)(g_qkv + ((size_t)n*512 + row0 + 8)*1936 + pos) =
                        __floats2half2_rn(acc[mf][nf][2] + b1, acc[mf][nf][3] + b1);
                }
            }
        }
        __syncthreads();
    }
}

// ---------------- fused axial attention v11: fp32 q/k smem, fp16 v smem ----------------
// byte offsets: qkT f32[44][260]@0 (45760) | vSh half[256][56]@45760 (28672) |
//               simS f32@74432 (30976) | rTh@105408 (12544) | rvS@117952 (22528) |
//               resS@140480 (45056) ; staging aliases qkT region
#define XB_V   45760
#define XB_SIM 74432
#define XB_RTH 105408
#define XB_RVP 117952
#define XB_RES 140480
#define AX_SMEM 185536

template<int AX>
__global__ void __launch_bounds__(1024,1) axial_kernel()
{
    extern __shared__ char smb[];
    float*  qkT  = (float*)smb;
    __half* vSh  = (__half*)(smb + XB_V);
    float*  simS = (float*)(smb + XB_SIM);
    const __half* rTh = (const __half*)(smb + XB_RTH);
    uint32_t* rvS = (uint32_t*)(smb + XB_RVP);
    float* resS = (float*)(smb + XB_RES);
    float* stg  = (float*)smb;          // epilogue staging (aliases qkT)

    const int t  = threadIdx.x;
    const int bb = blockIdx.x;
    const int n  = bb / 44;
    const int s  = bb - n*44;

    // load qkv slice + rel tables (+ residual for AX=1)
    {
        const __half* qsrc = g_qkv + (size_t)n*512*1936 + s*44;
        for (int idx = t; idx < 5632; idx += 1024) {
            int o = idx / 11, q = idx - o*11;
            uint2 u2 = *(const uint2*)(qsrc + (size_t)o*1936 + q*4);
            int g = o >> 7, wi = o & 127;
            if (wi < 64) {
                float2 va = h2f(u2.x), vb = h2f(u2.y);
                int col = g*64 + wi;
                qkT[(q*4+0)*260 + col] = va.x;
                qkT[(q*4+1)*260 + col] = va.y;
                qkT[(q*4+2)*260 + col] = vb.x;
                qkT[(q*4+3)*260 + col] = vb.y;
            } else {
                *(uint2*)(vSh + (g*64 + wi - 64)*56 + q*4) = u2;
            }
        }
        const uint32_t* rthG = (const uint32_t*)g_relTh[AX];
        uint32_t* rthS = (uint32_t*)(smb + XB_RTH);
        for (int idx = t; idx < 3132; idx += 1024) rthS[idx] = rthG[idx];
        for (int idx = t; idx < 5632; idx += 1024) rvS[idx] = g_rvP[AX][idx];
        if (AX == 1) {
            const float4* rsrc = (const float4*)(g_p + (size_t)n*IMGSZ + s*44);
            float4* rd = (float4*)resS;
            for (int idx = t; idx < 2816; idx += 1024) {
                int ch = idx / 11, q = idx - ch*11;
                rd[idx] = rsrc[ch*484 + q];
            }
        }
    }
    __syncthreads();

    // sim: thread handles (i,j) for a group PAIR (fp32 q/k — R15 code)
    for (int e2 = t; e2 < 3872; e2 += 1024) {
        int gp = e2 / 1936;
        int r = e2 - gp*1936;
        int i = r / 44;
        int j = r - i*44;
        const uint4* rq = (const uint4*)(rTh + (i - j + 43)*72);
        const uint4* rk = (const uint4*)(rTh + (j - i + 43)*72 + 32);
        float2 qk2[2], qr2[2], kr2[2];
        #pragma unroll
        for (int gg = 0; gg < 2; gg++) {
            qk2[gg] = make_float2(0.f, 0.f);
            qr2[gg] = make_float2(0.f, 0.f);
            kr2[gg] = make_float2(0.f, 0.f);
        }
        #pragma unroll
        for (int cc = 0; cc < 4; cc++) {
            uint4 rqu = rq[cc], rku = rk[cc];
            float2 rq0 = h2f(rqu.x), rq1 = h2f(rqu.y), rq2 = h2f(rqu.z), rq3 = h2f(rqu.w);
            float2 rk0 = h2f(rku.x), rk1 = h2f(rku.y), rk2 = h2f(rku.z), rk3 = h2f(rku.w);
            #pragma unroll
            for (int gg = 0; gg < 2; gg++) {
                int g = gp*2 + gg;
                const float4* qp = (const float4*)(qkT + i*260 + g*64) + 2*cc;
                const float4* kp = (const float4*)(qkT + j*260 + g*64 + 32) + 2*cc;
                float4 q4a = qp[0], q4b = qp[1];
                float4 k4a = kp[0], k4b = kp[1];
                fma2(qk2[gg], make_float2(q4a.x,q4a.y), make_float2(k4a.x,k4a.y));
                fma2(qk2[gg], make_float2(q4a.z,q4a.w), make_float2(k4a.z,k4a.w));
                fma2(qk2[gg], make_float2(q4b.x,q4b.y), make_float2(k4b.x,k4b.y));
                fma2(qk2[gg], make_float2(q4b.z,q4b.w), make_float2(k4b.z,k4b.w));
                fma2(qr2[gg], make_float2(q4a.x,q4a.y), rq0);
                fma2(qr2[gg], make_float2(q4a.z,q4a.w), rq1);
                fma2(qr2[gg], make_float2(q4b.x,q4b.y), rq2);
                fma2(qr2[gg], make_float2(q4b.z,q4b.w), rq3);
                fma2(kr2[gg], make_float2(k4a.x,k4a.y), rk0);
                fma2(kr2[gg], make_float2(k4a.z,k4a.w), rk1);
                fma2(kr2[gg], make_float2(k4b.x,k4b.y), rk2);
                fma2(kr2[gg], make_float2(k4b.z,k4b.w), rk3);
            }
        }
        #pragma unroll
        for (int gg = 0; gg < 2; gg++) {
            int g = gp*2 + gg;
            float qk = qk2[gg].x + qk2[gg].y;
            float qr = qr2[gg].x + qr2[gg].y;
            float kr = kr2[gg].x + kr2[gg].y;
            simS[g*1936 + r] = g_simA[AX][g]*qk + g_simA[AX][4+g]*qr + g_simA[AX][8+g]*kr + g_simBsum[AX][g];
        }
    }
    __syncthreads();

    // softmax: warp per row
    {
        const int wid = t >> 5, lane = t & 31;
        #pragma unroll
        for (int k = 0; k < 6; k++) {
            int r = wid + 32*k;
            if (r < 176) {
                float* row = simS + (r/44)*1936 + (r - (r/44)*44)*44;
                float v1 = row[lane];
                float v2 = (lane < 12) ? row[lane+32] : -1e30f;
                float m = fmaxf(v1, v2);
                #pragma unroll
                for (int off = 16; off; off >>= 1) m = fmaxf(m, __shfl_xor_sync(0xffffffffu, m, off));
                float e1 = __expf(v1 - m);
                float e2 = (lane < 12) ? __expf(v2 - m) : 0.f;
                float su = e1 + e2;
                #pragma unroll
                for (int off = 16; off; off >>= 1) su += __shfl_xor_sync(0xffffffffu, su, off);
                float inv = 1.f / su;
                row[lane] = e1 * inv;
                if (lane < 12) row[lane+32] = e2 * inv;
            }
        }
    }
    __syncthreads();

    // output: v from fp16 smem into regs (one-time converts, outside hot loop)
    {
        const int ch = t & 255, qtr = t >> 8;
        const int g = ch >> 6, c = ch & 63;
        float2 v2[22];
        {
            const uint4* vp = (const uint4*)(vSh + ch*56);
            #pragma unroll
            for (int q = 0; q < 5; q++) {
                uint4 u = vp[q];
                v2[4*q+0] = h2f(u.x); v2[4*q+1] = h2f(u.y);
                v2[4*q+2] = h2f(u.z); v2[4*q+3] = h2f(u.w);
            }
            uint2 tail = *(const uint2*)(vSh + ch*56 + 40);
            v2[20] = h2f(tail.x); v2[21] = h2f(tail.y);
        }
        const float aSV  = g_outA_sv[AX][ch];
        const float aSVE = g_outA_sve[AX][ch];
        const float bO   = g_outB[AX][ch];
        #pragma unroll 1
        for (int ii = 0; ii < 11; ii++) {
            int i = qtr*11 + ii;
            const float2* sr2 = (const float2*)(simS + g*1936 + i*44);
            int b0 = 43 - i;
            const uint32_t* wrow = rvS + (b0 & 1)*2816 + (b0 >> 1)*64 + c;
            float2 sv2 = make_float2(0.f, 0.f), sve2 = make_float2(0.f, 0.f);
            #pragma unroll
            for (int p = 0; p < 22; p++) {
                float2 s2 = sr2[p];
                fma2(sv2, s2, v2[p]);
                fma2(sve2, s2, h2f(wrow[p*64]));
            }
            float val = fmaf(aSV, sv2.x + sv2.y, fmaf(aSVE, sve2.x + sve2.y, bO));
            if (AX == 0) {
                stg[ch*44 + i] = val;
            } else {
                stg[i*256 + ch] = val + resS[ch*44 + i];
            }
        }
    }
    __syncthreads();
    if (AX == 0) {
        // fp16 stores to g_t1
        for (int idx = t; idx < 2816; idx += 1024) {
            int ch = idx / 11, q = idx - ch*11;
            float4 v4 = ((const float4*)stg)[idx];
            uint2 u;
            __half2 h0 = __floats2half2_rn(v4.x, v4.y);
            __half2 h1 = __floats2half2_rn(v4.z, v4.w);
            u.x = *reinterpret_cast<uint32_t*>(&h0);
            u.y = *reinterpret_cast<uint32_t*>(&h1);
            *(uint2*)(g_t1 + ((size_t)(n*256 + ch))*1936 + s*44 + q*4) = u;
        }
    } else {
        const size_t rowbase = ((size_t)MARGIN_LO + (size_t)n*PPX + (size_t)(s+1)*48 + 1)*256;
        for (int idx = t; idx < 11264; idx += 1024) {
            int i = idx >> 8, ch = idx & 255;
            g_xc[rowbase + (size_t)i*256 + ch] = __float2half(stg[i*256 + ch]);
        }
    }
}

// ---------------- tensor-core conv3x3 v3: fp16 single-pass ----------------
#define C3STAGE 14592
#define C3_B    6144
#define CONV_SMEM (3*C3STAGE + 1024)

__global__ void __launch_bounds__(512,1) conv_mma_kernel(const float* __restrict__ conv_b,
                                                         float* __restrict__ out)
{
    extern __shared__ char smc[];
    const uint32_t sbase = smem_to_u32(smc);
    const int t = threadIdx.x;
    const int wid = t >> 5, lane = t & 31;
    const int bb = blockIdx.x;
    const int n = bb / 18;
    const int widx = bb - n*18;
    const int pxw = widx * 128;
    const int wm = wid & 1, wn = wid >> 1;

    float* biasS = (float*)(smc + 3*C3STAGE);
    if (t < 256) biasS[t] = conv_b[t];

    const long long arow0 = (long long)MARGIN_LO + (long long)n*PPX + pxw;

    auto load_chunk = [&](int kc, int stage) {
        const int tap = kc >> 4, sub = kc & 15;
        const int offr = (tap/3 - 1)*48 + (tap%3 - 1);
        const long long abase = arow0 + offr;
        const uint32_t sA = sbase + stage*C3STAGE;
        const uint32_t sB = sA + C3_B;
        #pragma unroll
        for (int i = 0; i < 2; i++) {
            int o = t + 512*i;
            if (o < 256) {
                int half = o & 1;
                int row  = o >> 1;
                const __half* g = g_xc + ((size_t)(abase + row))*256 + sub*16 + half*8;
                cp16(sA + row*48 + half*16, g);
            } else if (o < 768) {
                int o2 = o - 256;
                int krow = o2 >> 5, unit = o2 & 31;
                const __half* g = g_wc + ((size_t)(tap*256 + sub*16 + krow))*256 + unit*8;
                cp16(sB + krow*528 + unit*16, g);
            }
        }
    };

    float acc[4][4][4];
    #pragma unroll
    for (int mf = 0; mf < 4; mf++)
        #pragma unroll
        for (int nf = 0; nf < 4; nf++)
            #pragma unroll
            for (int k = 0; k < 4; k++) acc[mf][nf][k] = 0.f;

    load_chunk(0, 0); CP_COMMIT();
    load_chunk(1, 1); CP_COMMIT();

    for (int kc = 0; kc < 144; kc++) {
        const int stage = kc % 3;
        if (kc + 2 < 144) { load_chunk(kc+2, (kc+2)%3); CP_COMMIT(); CP_WAIT(2); }
        else if (kc + 1 < 144) { CP_WAIT(1); }
        else { CP_WAIT(0); }
        __syncthreads();

        const uint32_t sA = sbase + stage*C3STAGE;
        const uint32_t sB = sA + C3_B;

        uint32_t A[4][4], B[4][2];
        #pragma unroll
        for (int mf = 0; mf < 4; mf++) {
            uint32_t a_off = (wm*64 + mf*16 + (lane & 15))*48 + (lane >> 4)*16;
            ldsm_x4(A[mf], sA + a_off);
        }
        #pragma unroll
        for (int nf = 0; nf < 4; nf++) {
            uint32_t b_off = (lane & 15)*528 + (wn*32 + nf*8)*2;
            ldsm_x2_t(B[nf], sB + b_off);
        }
        #pragma unroll
        for (int mf = 0; mf < 4; mf++)
            #pragma unroll
            for (int nf = 0; nf < 4; nf++)
                mma_f16(acc[mf][nf], A[mf], B[nf]);
        __syncthreads();
    }

    const int b_ = n >> 2, i2 = (n >> 1) & 1, j2 = n & 1;
    #pragma unroll
    for (int mf = 0; mf < 4; mf++) {
        #pragma unroll
        for (int half = 0; half < 2; half++) {
            int px = pxw + wm*64 + mf*16 + (lane >> 2) + half*8;
            int py = px / 48, pxx = px - py*48;
            bool valid = (py >= 1 && py <= 44) && (pxx >= 1 && pxx <= 44);
            if (!valid) continue;
            size_t ob = ((size_t)(b_*256))*7744 + (size_t)(i2*44 + (py-1))*88 + j2*44 + (pxx-1);
            #pragma unroll
            for (int nf = 0; nf < 4; nf++) {
                int co = wn*32 + nf*8 + (lane & 3)*2;
                out[ob + (size_t)co*7744]     = acc[mf][nf][half*2+0] + biasS[co];
                out[ob + (size_t)(co+1)*7744] = acc[mf][nf][half*2+1] + biasS[co+1];
            }
        }
    }
}

// ---------------- launch ----------------
extern "C" void kernel_launch(void* const* d_in, const int* in_sizes, int n_in,
                              void* d_out, int out_size)
{
    const float* x        = (const float*)d_in[0];
    const float* h_qkv_w  = (const float*)d_in[1];
    const float* h_bn_qkv = (const float*)d_in[2];
    const float* h_bn_sim = (const float*)d_in[3];
    const float* h_bn_out = (const float*)d_in[4];
    const float* h_rel    = (const float*)d_in[5];
    const float* w_qkv_w  = (const float*)d_in[6];
    const float* w_bn_qkv = (const float*)d_in[7];
    const float* w_bn_sim = (const float*)d_in[8];
    const float* w_bn_out = (const float*)d_in[9];
    const float* w_rel    = (const float*)d_in[10];
    const float* conv_w   = (const float*)d_in[11];
    const float* conv_b   = (const float*)d_in[12];
    float* out = (float*)d_out;

    cudaFuncSetAttribute(axial_kernel<0>,  cudaFuncAttributeMaxDynamicSharedMemorySize, AX_SMEM);
    cudaFuncSetAttribute(axial_kernel<1>,  cudaFuncAttributeMaxDynamicSharedMemorySize, AX_SMEM);
    cudaFuncSetAttribute(qkv_gemm_kernel,  cudaFuncAttributeMaxDynamicSharedMemorySize, GEMM_SMEM);
    cudaFuncSetAttribute(conv_mma_kernel,  cudaFuncAttributeMaxDynamicSharedMemorySize, CONV_SMEM);

    prep_kernel<<<(256*256*9 + 255)/256, 256>>>(h_qkv_w, h_bn_qkv, h_bn_sim, h_bn_out,
                                                w_qkv_w, w_bn_qkv, w_bn_sim, w_bn_out,
                                                conv_w, h_rel, w_rel);
    patchify_kernel<<<NPATCH*256, 256>>>(x);
    qkv_gemm_kernel<<<dim3(16,NPATCH), 512, GEMM_SMEM>>>(0);
    axial_kernel<0><<<NB, 1024, AX_SMEM>>>();
    transpose_kernel<<<NPATCH*256, 256>>>();
    qkv_gemm_kernel<<<dim3(16,NPATCH), 512, GEMM_SMEM>>>(1);
    axial_kernel<1><<<NB, 1024, AX_SMEM>>>();
    conv_mma_kernel<<<NPATCH*18, 512, CONV_SMEM>>>(conv_b, out);
}